// round 2
// baseline (speedup 1.0000x reference)
#include <cuda_runtime.h>
#include <math.h>

// ---------------- constants ----------------
constexpr int NSEQ  = 256;
constexpr int ROWS1 = 16384;                  // B*N = 64*256
constexpr size_t FS = (size_t)ROWS1 * 512;    // floats per tensor

// ---------------- scratch (static device memory; no allocs) ----------------
__device__ float g_f  [3 * FS];                    // projected features q,k,v
__device__ float g_s  [(size_t)512 * NSEQ * NSEQ]; // per-(h,b) score matrices
__device__ float g_att[FS];                        // attention output [B,N,h*d]
__device__ float g_norms[2 * 512 * NSEQ];          // qn, kn  [t][hb][n]
__device__ float g_vc[256];                        // [Vq(64), Cq(64), Vk(64), Ck(64)]
__device__ float g_part[2048];                     // stats partials [t][c][s][2]
__device__ float g_mu[3 * ROWS1];
__device__ float g_rs[3 * ROWS1];

__device__ __forceinline__ float warp_sum(float v) {
    #pragma unroll
    for (int o = 16; o; o >>= 1) v += __shfl_xor_sync(0xffffffffu, v, o);
    return v;
}

// ---------------- 1) LN row statistics: one warp per row ----------------
__global__ __launch_bounds__(256) void ln_stats_kernel(
    const float* __restrict__ q, const float* __restrict__ k, const float* __restrict__ v)
{
    int warp = threadIdx.x >> 5, lane = threadIdx.x & 31;
    int row = blockIdx.x * 8 + warp;          // 0..49151
    int t = row >> 14;
    int r = row & 16383;
    const float* src = (t == 0 ? q : (t == 1 ? k : v)) + (size_t)r * 512;

    float x[16];
    float s = 0.f;
    #pragma unroll
    for (int i = 0; i < 16; i++) { x[i] = src[lane + 32 * i]; s += x[i]; }
    s = warp_sum(s);
    float mu = s * (1.f / 512.f);
    float ss = 0.f;
    #pragma unroll
    for (int i = 0; i < 16; i++) { float d = x[i] - mu; ss += d * d; }
    ss = warp_sum(ss);
    if (!lane) {
        g_mu[row] = mu;
        g_rs[row] = rsqrtf(ss * (1.f / 512.f) + 1e-5f);
    }
}

// ---------------- 2/7) SGEMM 128x128x8 double-buffered, optional LN + norms ----------------
template<bool LN>
__global__ __launch_bounds__(256) void sgemm_kernel(
    const float* __restrict__ A,
    const float* __restrict__ q, const float* __restrict__ k, const float* __restrict__ v,
    const float* __restrict__ gma, const float* __restrict__ bta,
    const float* __restrict__ B, float* __restrict__ C, const float* __restrict__ bias)
{
    constexpr int BM = 128, BN = 128, BK = 8, N = 512, K = 512;
    __shared__ float As[2][BK * 132];
    __shared__ float Bs[2][BK * BN];

    int tid = threadIdx.x;
    int tCol = tid & 15, tRow = tid >> 4;
    int iRA = tid >> 1, iCA = tid & 1;
    int iRB = tid >> 5, iCB = tid & 31;

    int grow = blockIdx.y * BM;
    int t = 0;
    float mu = 0.f, rs = 0.f;
    const float* src;
    if (LN) {
        t = grow >> 14;
        int r0 = (grow & 16383) + iRA;
        src = (t == 0 ? q : (t == 1 ? k : v)) + (size_t)r0 * K;
        mu = g_mu[grow + iRA];
        rs = g_rs[grow + iRA];
    } else {
        src = A + (size_t)(grow + iRA) * K;
    }
    const float* Bbase = B + (size_t)blockIdx.x * BN + (size_t)iRB * N + iCB * 4;
    C += (size_t)blockIdx.y * BM * N + (size_t)blockIdx.x * BN;

    float acc[8][8] = {};
    float4 pA, pB;

    // prologue: tile 0
    pA = *(const float4*)(src + iCA * 4);
    if (LN) {
        float4 g4 = *(const float4*)(gma + iCA * 4);
        float4 b4 = *(const float4*)(bta + iCA * 4);
        pA.x = (pA.x - mu) * rs * g4.x + b4.x;
        pA.y = (pA.y - mu) * rs * g4.y + b4.y;
        pA.z = (pA.z - mu) * rs * g4.z + b4.z;
        pA.w = (pA.w - mu) * rs * g4.w + b4.w;
    }
    pB = *(const float4*)(Bbase);
    As[0][(iCA * 4 + 0) * 132 + iRA] = pA.x;
    As[0][(iCA * 4 + 1) * 132 + iRA] = pA.y;
    As[0][(iCA * 4 + 2) * 132 + iRA] = pA.z;
    As[0][(iCA * 4 + 3) * 132 + iRA] = pA.w;
    *(float4*)&Bs[0][iRB * BN + iCB * 4] = pB;
    __syncthreads();

    int buf = 0;
    for (int bk = 0; bk < K; bk += BK) {
        bool more = (bk + BK) < K;
        if (more) {
            int col = bk + BK + iCA * 4;
            pA = *(const float4*)(src + col);
            if (LN) {
                float4 g4 = *(const float4*)(gma + col);
                float4 b4 = *(const float4*)(bta + col);
                pA.x = (pA.x - mu) * rs * g4.x + b4.x;
                pA.y = (pA.y - mu) * rs * g4.y + b4.y;
                pA.z = (pA.z - mu) * rs * g4.z + b4.z;
                pA.w = (pA.w - mu) * rs * g4.w + b4.w;
            }
            pB = *(const float4*)(Bbase + (size_t)(bk + BK) * N);
        }
        #pragma unroll
        for (int kk = 0; kk < BK; kk++) {
            float4 m0 = *(const float4*)&As[buf][kk * 132 + tRow * 8];
            float4 m1 = *(const float4*)&As[buf][kk * 132 + tRow * 8 + 4];
            float4 n0 = *(const float4*)&Bs[buf][kk * BN + tCol * 8];
            float4 n1 = *(const float4*)&Bs[buf][kk * BN + tCol * 8 + 4];
            float rM[8] = {m0.x, m0.y, m0.z, m0.w, m1.x, m1.y, m1.z, m1.w};
            float rN[8] = {n0.x, n0.y, n0.z, n0.w, n1.x, n1.y, n1.z, n1.w};
            #pragma unroll
            for (int i = 0; i < 8; i++)
                #pragma unroll
                for (int j = 0; j < 8; j++)
                    acc[i][j] += rM[i] * rN[j];
        }
        if (more) {
            As[buf ^ 1][(iCA * 4 + 0) * 132 + iRA] = pA.x;
            As[buf ^ 1][(iCA * 4 + 1) * 132 + iRA] = pA.y;
            As[buf ^ 1][(iCA * 4 + 2) * 132 + iRA] = pA.z;
            As[buf ^ 1][(iCA * 4 + 3) * 132 + iRA] = pA.w;
            *(float4*)&Bs[buf ^ 1][iRB * BN + iCB * 4] = pB;
            __syncthreads();
            buf ^= 1;
        }
    }

    #pragma unroll
    for (int i = 0; i < 8; i++) {
        #pragma unroll
        for (int j = 0; j < 8; j += 4) {
            int col = tCol * 8 + j;
            float4 o = make_float4(acc[i][j], acc[i][j + 1], acc[i][j + 2], acc[i][j + 3]);
            if (!LN && bias) {
                const float* bp = bias + blockIdx.x * BN + col;
                o.x += bp[0]; o.y += bp[1]; o.z += bp[2]; o.w += bp[3];
            }
            *(float4*)(C + (size_t)(tRow * 8 + i) * N + col) = o;
        }
    }

    // fused per-head row norms for q,k projections
    if (LN && t < 2) {
        int h = blockIdx.x * 2 + (tCol >> 3);
        #pragma unroll
        for (int i = 0; i < 8; i++) {
            float ss = 0.f;
            #pragma unroll
            for (int j = 0; j < 8; j++) ss += acc[i][j] * acc[i][j];
            #pragma unroll
            for (int o = 4; o; o >>= 1) ss += __shfl_down_sync(0xffffffffu, ss, o, 8);
            if ((tCol & 7) == 0) {
                int r = ((grow & 16383) + tRow * 8 + i);
                int b = r >> 8, n = r & 255;
                g_norms[t * 131072 + (h * 64 + b) * 256 + n] = sqrtf(ss);
            }
        }
    }
}

// ---------------- 3) chunk statistics: one block per (tensor, chunk, sample) ----------------
__global__ __launch_bounds__(256) void stats_kernel()
{
    __shared__ float sE[256 * 64];
    __shared__ float red[256];
    __shared__ float smu[64];
    __shared__ float r3[3][8];

    int tid = threadIdx.x;
    int bx = blockIdx.x;              // 0..1023
    int t = bx >> 9;
    int rest = bx & 511;
    int c = rest >> 3;                // chunk 0..63
    int s = rest & 7;
    int h = c >> 3;
    int b = ((c & 7) << 3) + s;
    const float* base = g_f + (size_t)t * FS + (size_t)(b * 256) * 512 + h * 64;

    // column means over N=256
    {
        int i = tid & 63, grp = tid >> 6;
        float sm = 0.f;
        for (int n = grp; n < 256; n += 4) sm += base[(size_t)n * 512 + i];
        red[tid] = sm;
        __syncthreads();
        if (tid < 64)
            smu[tid] = (red[tid] + red[tid + 64] + red[tid + 128] + red[tid + 192]) * (1.f / 256.f);
        __syncthreads();
    }

    // load centered sample into smem (float4)
    for (int idx = tid; idx < 4096; idx += 256) {
        int n = idx >> 4, c4 = (idx & 15) * 4;
        float4 a = *(const float4*)(base + (size_t)n * 512 + c4);
        a.x -= smu[c4 + 0]; a.y -= smu[c4 + 1]; a.z -= smu[c4 + 2]; a.w -= smu[c4 + 3];
        *(float4*)&sE[n * 64 + c4] = a;
    }
    __syncthreads();

    // Gram matrix: 4x4 per thread over 16x16 thread grid
    int ti = tid >> 4, tj = tid & 15;
    float acc[4][4] = {};
    #pragma unroll 8
    for (int n = 0; n < 256; n++) {
        float4 a  = *(const float4*)&sE[n * 64 + ti * 4];
        float4 bb = *(const float4*)&sE[n * 64 + tj * 4];
        acc[0][0] += a.x * bb.x; acc[0][1] += a.x * bb.y; acc[0][2] += a.x * bb.z; acc[0][3] += a.x * bb.w;
        acc[1][0] += a.y * bb.x; acc[1][1] += a.y * bb.y; acc[1][2] += a.y * bb.z; acc[1][3] += a.y * bb.w;
        acc[2][0] += a.z * bb.x; acc[2][1] += a.z * bb.y; acc[2][2] += a.z * bb.z; acc[2][3] += a.z * bb.w;
        acc[3][0] += a.w * bb.x; acc[3][1] += a.w * bb.y; acc[3][2] += a.w * bb.z; acc[3][3] += a.w * bb.w;
    }

    float tot = 0.f, dsum = 0.f, vsum = 0.f;
    #pragma unroll
    for (int r = 0; r < 4; r++)
        #pragma unroll
        for (int r2 = 0; r2 < 4; r2++) tot += acc[r][r2] * acc[r][r2];
    if (ti == tj) {
        #pragma unroll
        for (int r = 0; r < 4; r++) {
            float gii = acc[r][r];
            dsum += gii * gii;
            float sig = sqrtf(gii * (1.f / 255.f) + 1e-8f);
            vsum += fmaxf(0.f, 1.f - sig);
        }
    }

    int w = tid >> 5, lane = tid & 31;
    float a0 = warp_sum(tot), a1 = warp_sum(dsum), a2 = warp_sum(vsum);
    if (!lane) { r3[0][w] = a0; r3[1][w] = a1; r3[2][w] = a2; }
    __syncthreads();
    if (tid == 0) {
        float T = 0.f, D = 0.f, V = 0.f;
        #pragma unroll
        for (int i = 0; i < 8; i++) { T += r3[0][i]; D += r3[1][i]; V += r3[2][i]; }
        g_part[bx * 2 + 0] = V * (1.f / 512.f);
        g_part[bx * 2 + 1] = (T - D) * (1.f / (255.f * 255.f * 64.f * 8.f));
    }
}

// deterministic reduce of per-sample partials
__global__ __launch_bounds__(256) void stats_reduce_kernel()
{
    int tid = threadIdx.x;              // (t,c,comp): t=tid>>7, c=(tid>>1)&63, comp=tid&1
    int t = tid >> 7, c = (tid >> 1) & 63, comp = tid & 1;
    float v = 0.f;
    #pragma unroll
    for (int s = 0; s < 8; s++)
        v += g_part[((t * 512 + c * 8 + s) * 2) + comp];
    g_vc[t * 128 + comp * 64 + c] = v;
}

// ---------------- 4) batched Q@K^T, 128x128 tile, cosine + scalar bias epilogue ----------------
__global__ __launch_bounds__(256) void qk_kernel(
    const float* __restrict__ cov_logit, const float* __restrict__ var_logit)
{
    __shared__ float Qs[64 * 132];    // [d][n]
    __shared__ float Ks[64 * 132];    // [d][m]
    int tid = threadIdx.x;
    int hb = blockIdx.z, h = hb >> 6, b = hb & 63, c = hb >> 3;
    int nt = blockIdx.y, mt = blockIdx.x;
    int tRow = tid >> 4, tCol = tid & 15;
    int lrow = tid >> 1, lpart = tid & 1;

    const float* qb = g_f + (size_t)(b * 256 + nt * 128) * 512 + h * 64;
    const float* kb = g_f + FS + (size_t)(b * 256 + mt * 128) * 512 + h * 64;

    #pragma unroll
    for (int j = 0; j < 8; j++) {
        int col = lpart * 32 + j * 4;
        float4 a = *(const float4*)(qb + (size_t)lrow * 512 + col);
        Qs[(col + 0) * 132 + lrow] = a.x;
        Qs[(col + 1) * 132 + lrow] = a.y;
        Qs[(col + 2) * 132 + lrow] = a.z;
        Qs[(col + 3) * 132 + lrow] = a.w;
        float4 kk = *(const float4*)(kb + (size_t)lrow * 512 + col);
        Ks[(col + 0) * 132 + lrow] = kk.x;
        Ks[(col + 1) * 132 + lrow] = kk.y;
        Ks[(col + 2) * 132 + lrow] = kk.z;
        Ks[(col + 3) * 132 + lrow] = kk.w;
    }
    __syncthreads();

    float acc[8][8] = {};
    #pragma unroll 8
    for (int k = 0; k < 64; k++) {
        float4 m0 = *(const float4*)&Qs[k * 132 + tRow * 8];
        float4 m1 = *(const float4*)&Qs[k * 132 + tRow * 8 + 4];
        float4 n0 = *(const float4*)&Ks[k * 132 + tCol * 8];
        float4 n1 = *(const float4*)&Ks[k * 132 + tCol * 8 + 4];
        float rM[8] = {m0.x, m0.y, m0.z, m0.w, m1.x, m1.y, m1.z, m1.w};
        float rN[8] = {n0.x, n0.y, n0.z, n0.w, n1.x, n1.y, n1.z, n1.w};
        #pragma unroll
        for (int i = 0; i < 8; i++)
            #pragma unroll
            for (int j = 0; j < 8; j++)
                acc[i][j] += rM[i] * rN[j];
    }

    float cw = 1.f / (1.f + expf(-*cov_logit));
    float vw = 1.f / (1.f + expf(-*var_logit));
    float cosw = 1.f - cw - vw;
    float biasv = cw * (g_vc[64 + c] * g_vc[192 + c]) + vw * (g_vc[c] * g_vc[128 + c]);

    float qinv[8], kinv[8];
    #pragma unroll
    for (int i = 0; i < 8; i++)
        qinv[i] = cosw / g_norms[hb * 256 + nt * 128 + tRow * 8 + i];
    #pragma unroll
    for (int j = 0; j < 8; j++)
        kinv[j] = 1.f / g_norms[131072 + hb * 256 + mt * 128 + tCol * 8 + j];

    float* sp = g_s + (size_t)hb * 65536;
    #pragma unroll
    for (int i = 0; i < 8; i++) {
        int n = nt * 128 + tRow * 8 + i;
        #pragma unroll
        for (int j = 0; j < 8; j += 4) {
            float4 o = make_float4(qinv[i] * acc[i][j + 0] * kinv[j + 0] + biasv,
                                   qinv[i] * acc[i][j + 1] * kinv[j + 1] + biasv,
                                   qinv[i] * acc[i][j + 2] * kinv[j + 2] + biasv,
                                   qinv[i] * acc[i][j + 3] * kinv[j + 3] + biasv);
            *(float4*)(sp + (size_t)n * 256 + mt * 128 + tCol * 8 + j) = o;
        }
    }
}

// ---------------- 5) batched S@V, 128x64 tile, K=256 in 4 chunks ----------------
__global__ __launch_bounds__(256) void sv_kernel()
{
    __shared__ float Ss[64 * 132];   // [m][n]
    __shared__ float Vs[64 * 68];    // [m][dd]
    int tid = threadIdx.x;
    int hb = blockIdx.y, h = hb >> 6, b = hb & 63;
    int rt = blockIdx.x;
    int tRow = tid >> 4, tCol = tid & 15;
    int lrow = tid >> 1, lpart = tid & 1;
    int vrow = tid >> 2, vq = tid & 3;

    const float* sp = g_f + 0;  // placeholder to keep compiler quiet
    (void)sp;
    const float* srow = g_s + (size_t)hb * 65536 + (size_t)(rt * 128) * 256;
    const float* vb = g_f + 2 * FS + (size_t)(b * 256) * 512 + h * 64;

    float acc[8][4] = {};
    for (int mc = 0; mc < 4; mc++) {
        #pragma unroll
        for (int j = 0; j < 8; j++) {
            int m = lpart * 32 + j * 4;
            float4 a = *(const float4*)(srow + (size_t)lrow * 256 + mc * 64 + m);
            Ss[(m + 0) * 132 + lrow] = a.x;
            Ss[(m + 1) * 132 + lrow] = a.y;
            Ss[(m + 2) * 132 + lrow] = a.z;
            Ss[(m + 3) * 132 + lrow] = a.w;
        }
        #pragma unroll
        for (int p = 0; p < 4; p++) {
            int dd = (vq * 4 + p) * 4;
            *(float4*)&Vs[vrow * 68 + dd] =
                *(const float4*)(vb + (size_t)(mc * 64 + vrow) * 512 + dd);
        }
        __syncthreads();
        #pragma unroll 8
        for (int m = 0; m < 64; m++) {
            float4 m0 = *(const float4*)&Ss[m * 132 + tRow * 8];
            float4 m1 = *(const float4*)&Ss[m * 132 + tRow * 8 + 4];
            float4 n0 = *(const float4*)&Vs[m * 68 + tCol * 4];
            float rM[8] = {m0.x, m0.y, m0.z, m0.w, m1.x, m1.y, m1.z, m1.w};
            float rN[4] = {n0.x, n0.y, n0.z, n0.w};
            #pragma unroll
            for (int i = 0; i < 8; i++)
                #pragma unroll
                for (int j = 0; j < 4; j++)
                    acc[i][j] += rM[i] * rN[j];
        }
        __syncthreads();
    }

    float* ob = g_att + (size_t)(b * 256 + rt * 128) * 512 + h * 64;
    #pragma unroll
    for (int i = 0; i < 8; i++) {
        float4 o = make_float4(acc[i][0], acc[i][1], acc[i][2], acc[i][3]);
        *(float4*)(ob + (size_t)(tRow * 8 + i) * 512 + tCol * 4) = o;
    }
}

// ---------------- launch ----------------
extern "C" void kernel_launch(void* const* d_in, const int* in_sizes, int n_in,
                              void* d_out, int out_size)
{
    const float* q   = (const float*)d_in[0];
    const float* k   = (const float*)d_in[1];
    const float* v   = (const float*)d_in[2];
    const float* gma = (const float*)d_in[3];
    const float* bta = (const float*)d_in[4];
    const float* Win = (const float*)d_in[5];
    const float* Wout= (const float*)d_in[6];
    const float* bout= (const float*)d_in[7];
    const float* covl= (const float*)d_in[8];
    const float* varl= (const float*)d_in[9];
    float* out = (float*)d_out;

    void *pf, *patt;
    cudaGetSymbolAddress(&pf, g_f);
    cudaGetSymbolAddress(&patt, g_att);

    ln_stats_kernel<<<6144, 256>>>(q, k, v);
    sgemm_kernel<true><<<dim3(4, 384), 256>>>(nullptr, q, k, v, gma, bta,
                                              Win, (float*)pf, nullptr);
    stats_kernel<<<1024, 256>>>();
    stats_reduce_kernel<<<1, 256>>>();
    qk_kernel<<<dim3(2, 2, 512), 256>>>(covl, varl);
    sv_kernel<<<dim3(2, 512), 256>>>();
    sgemm_kernel<false><<<dim3(4, 128), 256>>>((const float*)patt, nullptr, nullptr, nullptr,
                                               nullptr, nullptr, Wout, out, bout);
}

// round 3
// speedup vs baseline: 2.6028x; 2.6028x over previous
#include <cuda_runtime.h>
#include <math.h>
#include <stdint.h>

constexpr size_t FS = (size_t)16384 * 512;

__device__ float g_f[3 * FS];                       // projected features q,k,v
__device__ float g_s[(size_t)512 * 256 * 256];      // score matrices
__device__ float g_att[FS];                         // attention out [B,N,h*d]
__device__ float g_norms[2 * 512 * 256];            // qn,kn [t][hb][n]
__device__ float g_vc[256];                         // Vq,Cq,Vk,Ck
__device__ float g_part[2048];
__device__ float g_mu[49152];
__device__ float g_rs[49152];

__device__ __forceinline__ float warp_sum(float v) {
    #pragma unroll
    for (int o = 16; o; o >>= 1) v += __shfl_xor_sync(0xffffffffu, v, o);
    return v;
}

__device__ __forceinline__ float tf32r(float x) {
    uint32_t u;
    asm("cvt.rna.tf32.f32 %0, %1;" : "=r"(u) : "f"(x));
    return __uint_as_float(u);
}
__device__ __forceinline__ void tf32x4(float4& a) {
    a.x = tf32r(a.x); a.y = tf32r(a.y); a.z = tf32r(a.z); a.w = tf32r(a.w);
}
__device__ __forceinline__ void mma8(float c[4], const uint32_t a[4], uint32_t b0, uint32_t b1) {
    asm volatile(
        "mma.sync.aligned.m16n8k8.row.col.f32.tf32.tf32.f32 "
        "{%0,%1,%2,%3},{%4,%5,%6,%7},{%8,%9},{%0,%1,%2,%3};"
        : "+f"(c[0]), "+f"(c[1]), "+f"(c[2]), "+f"(c[3])
        : "r"(a[0]), "r"(a[1]), "r"(a[2]), "r"(a[3]), "r"(b0), "r"(b1));
}

// ---------------- 1) LN row statistics ----------------
__global__ __launch_bounds__(256) void ln_stats_kernel(
    const float* __restrict__ q, const float* __restrict__ k, const float* __restrict__ v)
{
    int warp = threadIdx.x >> 5, lane = threadIdx.x & 31;
    int row = blockIdx.x * 8 + warp;
    int t = row >> 14, r = row & 16383;
    const float* src = (t == 0 ? q : (t == 1 ? k : v)) + (size_t)r * 512;
    float x[16], s = 0.f;
    #pragma unroll
    for (int i = 0; i < 16; i++) { x[i] = src[lane + 32 * i]; s += x[i]; }
    s = warp_sum(s);
    float mu = s * (1.f / 512.f), ss = 0.f;
    #pragma unroll
    for (int i = 0; i < 16; i++) { float d = x[i] - mu; ss += d * d; }
    ss = warp_sum(ss);
    if (!lane) { g_mu[row] = mu; g_rs[row] = rsqrtf(ss * (1.f / 512.f) + 1e-5f); }
}

// ---------------- 2/7) tf32 GEMM 128x128, BK=16, LN fused ----------------
template<bool LN>
__global__ __launch_bounds__(256) void mm_kernel(
    const float* __restrict__ A,
    const float* __restrict__ q, const float* __restrict__ kk_, const float* __restrict__ vv_,
    const float* __restrict__ gma, const float* __restrict__ bta,
    const float* __restrict__ B, float* __restrict__ C, const float* __restrict__ bias)
{
    __shared__ float As[2][128 * 20];   // [m][k], pad 20 -> frag banks 4g+t4
    __shared__ float Bs[2][16 * 136];   // [k][n], pad 136 -> frag banks 8t4+g

    int tid = threadIdx.x, lane = tid & 31, wid = tid >> 5;
    int g = lane >> 2, t4 = lane & 3;
    int wm = (wid >> 1) * 32, wn = (wid & 1) * 64;
    int bx = blockIdx.x;
    int grow = blockIdx.y * 128;

    int arow = tid >> 2, ac4 = (tid & 3) * 4;
    const float* srcA[2];
    float mu[2], rs[2];
    int t = 0;
    if (LN) {
        t = grow >> 14;
        int r0 = grow & 16383;
        const float* base = (t == 0 ? q : (t == 1 ? kk_ : vv_));
        #pragma unroll
        for (int l = 0; l < 2; l++) {
            int rr = r0 + l * 64 + arow;
            srcA[l] = base + (size_t)rr * 512;
            mu[l] = g_mu[grow + l * 64 + arow];
            rs[l] = g_rs[grow + l * 64 + arow];
        }
    } else {
        #pragma unroll
        for (int l = 0; l < 2; l++)
            srcA[l] = A + (size_t)(grow + l * 64 + arow) * 512;
    }
    const float* Bbase = B + (size_t)bx * 128 + lane * 4;

    float acc[2][8][4] = {};
    float4 pA[2], pB[2];

    // prologue loads
    #pragma unroll
    for (int l = 0; l < 2; l++) {
        float4 x = *(const float4*)(srcA[l] + ac4);
        if (LN) {
            float4 g4 = *(const float4*)(gma + ac4);
            float4 b4 = *(const float4*)(bta + ac4);
            x.x = (x.x - mu[l]) * rs[l] * g4.x + b4.x;
            x.y = (x.y - mu[l]) * rs[l] * g4.y + b4.y;
            x.z = (x.z - mu[l]) * rs[l] * g4.z + b4.z;
            x.w = (x.w - mu[l]) * rs[l] * g4.w + b4.w;
        }
        tf32x4(x);
        *(float4*)&As[0][(l * 64 + arow) * 20 + ac4] = x;
        float4 y = *(const float4*)(Bbase + (size_t)(l * 8 + wid) * 512);
        tf32x4(y);
        *(float4*)&Bs[0][(l * 8 + wid) * 136 + lane * 4] = y;
    }
    __syncthreads();

    int buf = 0;
    for (int bk = 0; bk < 512; bk += 16) {
        bool more = (bk + 16) < 512;
        if (more) {
            #pragma unroll
            for (int l = 0; l < 2; l++) {
                float4 x = *(const float4*)(srcA[l] + bk + 16 + ac4);
                if (LN) {
                    float4 g4 = *(const float4*)(gma + bk + 16 + ac4);
                    float4 b4 = *(const float4*)(bta + bk + 16 + ac4);
                    x.x = (x.x - mu[l]) * rs[l] * g4.x + b4.x;
                    x.y = (x.y - mu[l]) * rs[l] * g4.y + b4.y;
                    x.z = (x.z - mu[l]) * rs[l] * g4.z + b4.z;
                    x.w = (x.w - mu[l]) * rs[l] * g4.w + b4.w;
                }
                tf32x4(x);
                pA[l] = x;
                float4 y = *(const float4*)(Bbase + (size_t)(bk + 16 + l * 8 + wid) * 512);
                tf32x4(y);
                pB[l] = y;
            }
        }
        #pragma unroll
        for (int ks = 0; ks < 2; ks++) {
            int kb = ks * 8;
            uint32_t af[2][4];
            #pragma unroll
            for (int mi = 0; mi < 2; mi++) {
                const float* ap = &As[buf][(wm + mi * 16) * 20 + kb];
                af[mi][0] = __float_as_uint(ap[g * 20 + t4]);
                af[mi][1] = __float_as_uint(ap[(g + 8) * 20 + t4]);
                af[mi][2] = __float_as_uint(ap[g * 20 + t4 + 4]);
                af[mi][3] = __float_as_uint(ap[(g + 8) * 20 + t4 + 4]);
            }
            #pragma unroll
            for (int ni = 0; ni < 8; ni++) {
                uint32_t b0 = __float_as_uint(Bs[buf][(kb + t4) * 136 + wn + ni * 8 + g]);
                uint32_t b1 = __float_as_uint(Bs[buf][(kb + t4 + 4) * 136 + wn + ni * 8 + g]);
                mma8(acc[0][ni], af[0], b0, b1);
                mma8(acc[1][ni], af[1], b0, b1);
            }
        }
        if (more) {
            #pragma unroll
            for (int l = 0; l < 2; l++) {
                *(float4*)&As[buf ^ 1][(l * 64 + arow) * 20 + ac4] = pA[l];
                *(float4*)&Bs[buf ^ 1][(l * 8 + wid) * 136 + lane * 4] = pB[l];
            }
            __syncthreads();
            buf ^= 1;
        }
    }

    #pragma unroll
    for (int mi = 0; mi < 2; mi++) {
        #pragma unroll
        for (int ni = 0; ni < 8; ni++) {
            int col = bx * 128 + wn + ni * 8 + 2 * t4;
            float2 o0 = make_float2(acc[mi][ni][0], acc[mi][ni][1]);
            float2 o1 = make_float2(acc[mi][ni][2], acc[mi][ni][3]);
            if (!LN && bias) {
                float2 bb = *(const float2*)(bias + col);
                o0.x += bb.x; o0.y += bb.y; o1.x += bb.x; o1.y += bb.y;
            }
            int r0 = grow + wm + mi * 16 + g;
            *(float2*)(C + (size_t)r0 * 512 + col) = o0;
            *(float2*)(C + (size_t)(r0 + 8) * 512 + col) = o1;
        }
    }

    if (LN && t < 2) {
        int h = bx * 2 + (wid & 1);
        #pragma unroll
        for (int mi = 0; mi < 2; mi++) {
            #pragma unroll
            for (int half = 0; half < 2; half++) {
                float s = 0.f;
                #pragma unroll
                for (int ni = 0; ni < 8; ni++) {
                    float x = acc[mi][ni][2 * half], y = acc[mi][ni][2 * half + 1];
                    s += x * x + y * y;
                }
                s += __shfl_xor_sync(0xffffffffu, s, 1);
                s += __shfl_xor_sync(0xffffffffu, s, 2);
                if (t4 == 0) {
                    int gr = grow + wm + mi * 16 + g + 8 * half;
                    int r = gr & 16383, bb = r >> 8, n = r & 255;
                    g_norms[t * 131072 + (h * 64 + bb) * 256 + n] = sqrtf(s);
                }
            }
        }
    }
}

// ---------------- 3) chunk statistics (fp32 SIMT) ----------------
__global__ __launch_bounds__(256) void stats_kernel()
{
    __shared__ float sE[256 * 64];
    __shared__ float red[256];
    __shared__ float smu[64];
    __shared__ float r3[3][8];

    int tid = threadIdx.x;
    int bx = blockIdx.x;
    int t = bx >> 9;
    int rest = bx & 511;
    int c = rest >> 3, s = rest & 7;
    int h = c >> 3, b = ((c & 7) << 3) + s;
    const float* base = g_f + (size_t)t * FS + (size_t)(b * 256) * 512 + h * 64;

    {
        int i = tid & 63, grp = tid >> 6;
        float sm = 0.f;
        for (int n = grp; n < 256; n += 4) sm += base[(size_t)n * 512 + i];
        red[tid] = sm;
        __syncthreads();
        if (tid < 64)
            smu[tid] = (red[tid] + red[tid + 64] + red[tid + 128] + red[tid + 192]) * (1.f / 256.f);
        __syncthreads();
    }

    for (int idx = tid; idx < 4096; idx += 256) {
        int n = idx >> 4, c4 = (idx & 15) * 4;
        float4 a = *(const float4*)(base + (size_t)n * 512 + c4);
        a.x -= smu[c4 + 0]; a.y -= smu[c4 + 1]; a.z -= smu[c4 + 2]; a.w -= smu[c4 + 3];
        *(float4*)&sE[n * 64 + c4] = a;
    }
    __syncthreads();

    int ti = tid >> 4, tj = tid & 15;
    float acc[4][4] = {};
    #pragma unroll 8
    for (int n = 0; n < 256; n++) {
        float4 a  = *(const float4*)&sE[n * 64 + ti * 4];
        float4 bb = *(const float4*)&sE[n * 64 + tj * 4];
        acc[0][0] += a.x * bb.x; acc[0][1] += a.x * bb.y; acc[0][2] += a.x * bb.z; acc[0][3] += a.x * bb.w;
        acc[1][0] += a.y * bb.x; acc[1][1] += a.y * bb.y; acc[1][2] += a.y * bb.z; acc[1][3] += a.y * bb.w;
        acc[2][0] += a.z * bb.x; acc[2][1] += a.z * bb.y; acc[2][2] += a.z * bb.z; acc[2][3] += a.z * bb.w;
        acc[3][0] += a.w * bb.x; acc[3][1] += a.w * bb.y; acc[3][2] += a.w * bb.z; acc[3][3] += a.w * bb.w;
    }

    float tot = 0.f, dsum = 0.f, vsum = 0.f;
    #pragma unroll
    for (int r = 0; r < 4; r++)
        #pragma unroll
        for (int r2 = 0; r2 < 4; r2++) tot += acc[r][r2] * acc[r][r2];
    if (ti == tj) {
        #pragma unroll
        for (int r = 0; r < 4; r++) {
            float gii = acc[r][r];
            dsum += gii * gii;
            float sig = sqrtf(gii * (1.f / 255.f) + 1e-8f);
            vsum += fmaxf(0.f, 1.f - sig);
        }
    }

    int w = tid >> 5, lane = tid & 31;
    float a0 = warp_sum(tot), a1 = warp_sum(dsum), a2 = warp_sum(vsum);
    if (!lane) { r3[0][w] = a0; r3[1][w] = a1; r3[2][w] = a2; }
    __syncthreads();
    if (tid == 0) {
        float T = 0.f, D = 0.f, V = 0.f;
        #pragma unroll
        for (int i = 0; i < 8; i++) { T += r3[0][i]; D += r3[1][i]; V += r3[2][i]; }
        g_part[bx * 2 + 0] = V * (1.f / 512.f);
        g_part[bx * 2 + 1] = (T - D) * (1.f / (255.f * 255.f * 64.f * 8.f));
    }
}

__global__ __launch_bounds__(256) void stats_reduce_kernel()
{
    int tid = threadIdx.x;
    int t = tid >> 7, c = (tid >> 1) & 63, comp = tid & 1;
    float v = 0.f;
    #pragma unroll
    for (int s = 0; s < 8; s++)
        v += g_part[((t * 512 + c * 8 + s) * 2) + comp];
    g_vc[t * 128 + comp * 64 + c] = v;
}

// ---------------- 4) QK^T tf32, 128x128 tile, d=64 resident ----------------
__global__ __launch_bounds__(256) void qk_kernel(
    const float* __restrict__ cl, const float* __restrict__ vl)
{
    extern __shared__ float sh[];
    float* Qs = sh;              // [128][68]
    float* Ks = sh + 128 * 68;   // [128][68]

    int tid = threadIdx.x, lane = tid & 31, wid = tid >> 5;
    int g = lane >> 2, t4 = lane & 3;
    int wm = (wid >> 1) * 32, wn = (wid & 1) * 64;
    int hb = blockIdx.z, h = hb >> 6, b = hb & 63, c = hb >> 3;
    int nt = blockIdx.y, mt = blockIdx.x;

    const float* qb = g_f + (size_t)(b * 256 + nt * 128) * 512 + h * 64;
    const float* kb = g_f + FS + (size_t)(b * 256 + mt * 128) * 512 + h * 64;
    int lrow = tid >> 4, lc4 = (tid & 15) * 4;

    #pragma unroll
    for (int l = 0; l < 8; l++) {
        int row = l * 16 + lrow;
        float4 a = *(const float4*)(qb + (size_t)row * 512 + lc4);
        tf32x4(a);
        *(float4*)&Qs[row * 68 + lc4] = a;
        float4 kkv = *(const float4*)(kb + (size_t)row * 512 + lc4);
        tf32x4(kkv);
        *(float4*)&Ks[row * 68 + lc4] = kkv;
    }
    __syncthreads();

    float acc[2][8][4] = {};
    #pragma unroll
    for (int ks = 0; ks < 8; ks++) {
        int kb8 = ks * 8;
        uint32_t af[2][4];
        #pragma unroll
        for (int mi = 0; mi < 2; mi++) {
            const float* ap = &Qs[(wm + mi * 16) * 68 + kb8];
            af[mi][0] = __float_as_uint(ap[g * 68 + t4]);
            af[mi][1] = __float_as_uint(ap[(g + 8) * 68 + t4]);
            af[mi][2] = __float_as_uint(ap[g * 68 + t4 + 4]);
            af[mi][3] = __float_as_uint(ap[(g + 8) * 68 + t4 + 4]);
        }
        #pragma unroll
        for (int ni = 0; ni < 8; ni++) {
            uint32_t b0 = __float_as_uint(Ks[(wn + ni * 8 + g) * 68 + kb8 + t4]);
            uint32_t b1 = __float_as_uint(Ks[(wn + ni * 8 + g) * 68 + kb8 + t4 + 4]);
            mma8(acc[0][ni], af[0], b0, b1);
            mma8(acc[1][ni], af[1], b0, b1);
        }
    }

    float cw = 1.f / (1.f + expf(-cl[0]));
    float vw = 1.f / (1.f + expf(-vl[0]));
    float cosw = 1.f - cw - vw;
    float biasv = cw * (g_vc[64 + c] * g_vc[192 + c]) + vw * (g_vc[c] * g_vc[128 + c]);

    float qs_[2][2];
    #pragma unroll
    for (int mi = 0; mi < 2; mi++)
        #pragma unroll
        for (int half = 0; half < 2; half++) {
            int n = nt * 128 + wm + mi * 16 + g + 8 * half;
            qs_[mi][half] = cosw / g_norms[hb * 256 + n];
        }

    float* sp = g_s + (size_t)hb * 65536;
    #pragma unroll
    for (int ni = 0; ni < 8; ni++) {
        int m0 = mt * 128 + wn + ni * 8 + 2 * t4;
        float ki0 = 1.f / g_norms[131072 + hb * 256 + m0];
        float ki1 = 1.f / g_norms[131072 + hb * 256 + m0 + 1];
        #pragma unroll
        for (int mi = 0; mi < 2; mi++) {
            #pragma unroll
            for (int half = 0; half < 2; half++) {
                int n = nt * 128 + wm + mi * 16 + g + 8 * half;
                float2 o = make_float2(
                    qs_[mi][half] * acc[mi][ni][2 * half] * ki0 + biasv,
                    qs_[mi][half] * acc[mi][ni][2 * half + 1] * ki1 + biasv);
                *(float2*)(sp + (size_t)n * 256 + m0) = o;
            }
        }
    }
}

// ---------------- 5) S@V tf32, 128x64 tile, K=256 chunked by 32 ----------------
__global__ __launch_bounds__(256) void sv_kernel()
{
    __shared__ float Ss[128 * 36];   // [n][k], pad 36
    __shared__ float Vs[32 * 72];    // [k][dd], pad 72

    int tid = threadIdx.x, lane = tid & 31, wid = tid >> 5;
    int g = lane >> 2, t4 = lane & 3;
    int wm = (wid >> 1) * 32, wn = (wid & 1) * 32;
    int hb = blockIdx.y, h = hb >> 6, b = hb & 63;
    int rt = blockIdx.x;

    const float* sp = g_s + (size_t)hb * 65536 + (size_t)(rt * 128) * 256;
    const float* vb = g_f + 2 * FS + (size_t)(b * 256) * 512 + h * 64;

    int srow = tid >> 3, sc4 = (tid & 7) * 4;
    int vk = tid >> 4, vn4 = (tid & 15) * 4;

    float acc[2][4][4] = {};
    for (int mc = 0; mc < 8; mc++) {
        #pragma unroll
        for (int l = 0; l < 4; l++) {
            int row = l * 32 + srow;
            float4 a = *(const float4*)(sp + (size_t)row * 256 + mc * 32 + sc4);
            tf32x4(a);
            *(float4*)&Ss[row * 36 + sc4] = a;
        }
        #pragma unroll
        for (int l = 0; l < 2; l++) {
            int k = l * 16 + vk;
            float4 a = *(const float4*)(vb + (size_t)(mc * 32 + k) * 512 + vn4);
            tf32x4(a);
            *(float4*)&Vs[k * 72 + vn4] = a;
        }
        __syncthreads();
        #pragma unroll
        for (int ks = 0; ks < 4; ks++) {
            int kb8 = ks * 8;
            uint32_t af[2][4];
            #pragma unroll
            for (int mi = 0; mi < 2; mi++) {
                const float* ap = &Ss[(wm + mi * 16) * 36 + kb8];
                af[mi][0] = __float_as_uint(ap[g * 36 + t4]);
                af[mi][1] = __float_as_uint(ap[(g + 8) * 36 + t4]);
                af[mi][2] = __float_as_uint(ap[g * 36 + t4 + 4]);
                af[mi][3] = __float_as_uint(ap[(g + 8) * 36 + t4 + 4]);
            }
            #pragma unroll
            for (int ni = 0; ni < 4; ni++) {
                uint32_t b0 = __float_as_uint(Vs[(kb8 + t4) * 72 + wn + ni * 8 + g]);
                uint32_t b1 = __float_as_uint(Vs[(kb8 + t4 + 4) * 72 + wn + ni * 8 + g]);
                mma8(acc[0][ni], af[0], b0, b1);
                mma8(acc[1][ni], af[1], b0, b1);
            }
        }
        __syncthreads();
    }

    #pragma unroll
    for (int mi = 0; mi < 2; mi++) {
        #pragma unroll
        for (int ni = 0; ni < 4; ni++) {
            int col = wn + ni * 8 + 2 * t4;
            int n0 = rt * 128 + wm + mi * 16 + g;
            *(float2*)(g_att + (size_t)(b * 256 + n0) * 512 + h * 64 + col) =
                make_float2(acc[mi][ni][0], acc[mi][ni][1]);
            *(float2*)(g_att + (size_t)(b * 256 + n0 + 8) * 512 + h * 64 + col) =
                make_float2(acc[mi][ni][2], acc[mi][ni][3]);
        }
    }
}

// ---------------- launch ----------------
extern "C" void kernel_launch(void* const* d_in, const int* in_sizes, int n_in,
                              void* d_out, int out_size)
{
    const float* q   = (const float*)d_in[0];
    const float* k   = (const float*)d_in[1];
    const float* v   = (const float*)d_in[2];
    const float* gma = (const float*)d_in[3];
    const float* bta = (const float*)d_in[4];
    const float* Win = (const float*)d_in[5];
    const float* Wout= (const float*)d_in[6];
    const float* bout= (const float*)d_in[7];
    const float* covl= (const float*)d_in[8];
    const float* varl= (const float*)d_in[9];
    float* out = (float*)d_out;

    void *pf, *patt;
    cudaGetSymbolAddress(&pf, g_f);
    cudaGetSymbolAddress(&patt, g_att);

    static bool attr_set = false;
    if (!attr_set) {
        cudaFuncSetAttribute(qk_kernel, cudaFuncAttributeMaxDynamicSharedMemorySize,
                             2 * 128 * 68 * 4);
        attr_set = true;
    }

    ln_stats_kernel<<<6144, 256>>>(q, k, v);
    mm_kernel<true><<<dim3(4, 384), 256>>>(nullptr, q, k, v, gma, bta,
                                           Win, (float*)pf, nullptr);
    stats_kernel<<<1024, 256>>>();
    stats_reduce_kernel<<<1, 256>>>();
    qk_kernel<<<dim3(2, 2, 512), 256, 2 * 128 * 68 * 4>>>(covl, varl);
    sv_kernel<<<dim3(2, 512), 256>>>();
    mm_kernel<false><<<dim3(4, 128), 256>>>((const float*)patt, nullptr, nullptr, nullptr,
                                            nullptr, nullptr, Wout, out, bout);
}

// round 4
// speedup vs baseline: 2.7370x; 1.0516x over previous
#include <cuda_runtime.h>
#include <math.h>
#include <stdint.h>

constexpr size_t FS = (size_t)16384 * 512;

__device__ float g_xn[3 * FS];                      // LN output (tf32-rounded)
__device__ float g_f[3 * FS];                       // projected features (tf32-rounded)
__device__ float g_s[(size_t)512 * 256 * 256];      // scores (tf32-rounded)
__device__ float g_att[FS];                         // attention out (tf32-rounded)
__device__ float g_win[512 * 512];                  // W_in rounded
__device__ float g_wout[512 * 512];                 // W_out rounded
__device__ float g_norms[2 * 512 * 256];            // qn,kn [t][hb][n]
__device__ float g_vc[256];                         // Vq,Cq,Vk,Ck
__device__ float g_part[2048];

__device__ __forceinline__ float warp_sum(float v) {
    #pragma unroll
    for (int o = 16; o; o >>= 1) v += __shfl_xor_sync(0xffffffffu, v, o);
    return v;
}
__device__ __forceinline__ float tf32r(float x) {
    uint32_t u;
    asm("cvt.rna.tf32.f32 %0, %1;" : "=r"(u) : "f"(x));
    return __uint_as_float(u);
}
__device__ __forceinline__ void mma8(float c[4], const uint32_t a[4], uint32_t b0, uint32_t b1) {
    asm volatile(
        "mma.sync.aligned.m16n8k8.row.col.f32.tf32.tf32.f32 "
        "{%0,%1,%2,%3},{%4,%5,%6,%7},{%8,%9},{%0,%1,%2,%3};"
        : "+f"(c[0]), "+f"(c[1]), "+f"(c[2]), "+f"(c[3])
        : "r"(a[0]), "r"(a[1]), "r"(a[2]), "r"(a[3]), "r"(b0), "r"(b1));
}

// ---------------- 0) round weights once ----------------
__global__ __launch_bounds__(256) void wround_kernel(
    const float* __restrict__ Win, const float* __restrict__ Wout)
{
    int idx = (blockIdx.x * 256 + threadIdx.x) * 4;   // 256K elems each
    float4 a = *(const float4*)(Win + idx);
    a.x = tf32r(a.x); a.y = tf32r(a.y); a.z = tf32r(a.z); a.w = tf32r(a.w);
    *(float4*)(g_win + idx) = a;
    float4 b = *(const float4*)(Wout + idx);
    b.x = tf32r(b.x); b.y = tf32r(b.y); b.z = tf32r(b.z); b.w = tf32r(b.w);
    *(float4*)(g_wout + idx) = b;
}

// ---------------- 1) LayerNorm, writes tf32-rounded output ----------------
__global__ __launch_bounds__(256) void ln_kernel(
    const float* __restrict__ q, const float* __restrict__ k, const float* __restrict__ v,
    const float* __restrict__ gma, const float* __restrict__ bta)
{
    int warp = threadIdx.x >> 5, lane = threadIdx.x & 31;
    int row = blockIdx.x * 8 + warp;
    int t = row >> 14, r = row & 16383;
    const float* src = (t == 0 ? q : (t == 1 ? k : v)) + (size_t)r * 512;
    float x[16], s = 0.f;
    #pragma unroll
    for (int i = 0; i < 16; i++) { x[i] = src[lane + 32 * i]; s += x[i]; }
    s = warp_sum(s);
    float mu = s * (1.f / 512.f), ss = 0.f;
    #pragma unroll
    for (int i = 0; i < 16; i++) { float d = x[i] - mu; ss += d * d; }
    ss = warp_sum(ss);
    float rs = rsqrtf(ss * (1.f / 512.f) + 1e-5f);
    float* dst = g_xn + (size_t)row * 512;
    #pragma unroll
    for (int i = 0; i < 16; i++) {
        int c = lane + 32 * i;
        dst[c] = tf32r((x[i] - mu) * rs * gma[c] + bta[c]);
    }
}

// ---------------- 2/7) tf32 GEMM 128x128, BK=16, no cvt in loop ----------------
template<bool PROJ>
__global__ __launch_bounds__(256) void mm_kernel(
    const float* __restrict__ A, const float* __restrict__ B,
    float* __restrict__ C, const float* __restrict__ bias)
{
    __shared__ float As[2][128 * 20];
    __shared__ float Bs[2][16 * 136];

    int tid = threadIdx.x, lane = tid & 31, wid = tid >> 5;
    int g = lane >> 2, t4 = lane & 3;
    int wm = (wid >> 1) * 32, wn = (wid & 1) * 64;
    int bx = blockIdx.x;
    int grow = blockIdx.y * 128;

    int arow = tid >> 2, ac4 = (tid & 3) * 4;
    const float* srcA[2];
    #pragma unroll
    for (int l = 0; l < 2; l++)
        srcA[l] = A + (size_t)(grow + l * 64 + arow) * 512;
    const float* Bbase = B + (size_t)bx * 128 + lane * 4;

    float acc[2][8][4] = {};
    float4 pA[2], pB[2];

    #pragma unroll
    for (int l = 0; l < 2; l++) {
        *(float4*)&As[0][(l * 64 + arow) * 20 + ac4] = *(const float4*)(srcA[l] + ac4);
        *(float4*)&Bs[0][(l * 8 + wid) * 136 + lane * 4] =
            *(const float4*)(Bbase + (size_t)(l * 8 + wid) * 512);
    }
    __syncthreads();

    int buf = 0;
    for (int bk = 0; bk < 512; bk += 16) {
        bool more = (bk + 16) < 512;
        if (more) {
            #pragma unroll
            for (int l = 0; l < 2; l++) {
                pA[l] = *(const float4*)(srcA[l] + bk + 16 + ac4);
                pB[l] = *(const float4*)(Bbase + (size_t)(bk + 16 + l * 8 + wid) * 512);
            }
        }
        #pragma unroll
        for (int ks = 0; ks < 2; ks++) {
            int kb = ks * 8;
            uint32_t af[2][4];
            #pragma unroll
            for (int mi = 0; mi < 2; mi++) {
                const float* ap = &As[buf][(wm + mi * 16) * 20 + kb];
                af[mi][0] = __float_as_uint(ap[g * 20 + t4]);
                af[mi][1] = __float_as_uint(ap[(g + 8) * 20 + t4]);
                af[mi][2] = __float_as_uint(ap[g * 20 + t4 + 4]);
                af[mi][3] = __float_as_uint(ap[(g + 8) * 20 + t4 + 4]);
            }
            #pragma unroll
            for (int ni = 0; ni < 8; ni++) {
                uint32_t b0 = __float_as_uint(Bs[buf][(kb + t4) * 136 + wn + ni * 8 + g]);
                uint32_t b1 = __float_as_uint(Bs[buf][(kb + t4 + 4) * 136 + wn + ni * 8 + g]);
                mma8(acc[0][ni], af[0], b0, b1);
                mma8(acc[1][ni], af[1], b0, b1);
            }
        }
        if (more) {
            #pragma unroll
            for (int l = 0; l < 2; l++) {
                *(float4*)&As[buf ^ 1][(l * 64 + arow) * 20 + ac4] = pA[l];
                *(float4*)&Bs[buf ^ 1][(l * 8 + wid) * 136 + lane * 4] = pB[l];
            }
            __syncthreads();
            buf ^= 1;
        }
    }

    if (PROJ) {
        // round outputs to tf32 (once per element), then store + fused norms
        #pragma unroll
        for (int mi = 0; mi < 2; mi++)
            #pragma unroll
            for (int ni = 0; ni < 8; ni++)
                #pragma unroll
                for (int p = 0; p < 4; p++)
                    acc[mi][ni][p] = tf32r(acc[mi][ni][p]);
    }

    #pragma unroll
    for (int mi = 0; mi < 2; mi++) {
        #pragma unroll
        for (int ni = 0; ni < 8; ni++) {
            int col = bx * 128 + wn + ni * 8 + 2 * t4;
            float2 o0 = make_float2(acc[mi][ni][0], acc[mi][ni][1]);
            float2 o1 = make_float2(acc[mi][ni][2], acc[mi][ni][3]);
            if (!PROJ) {
                float2 bb = *(const float2*)(bias + col);
                o0.x += bb.x; o0.y += bb.y; o1.x += bb.x; o1.y += bb.y;
            }
            int r0 = grow + wm + mi * 16 + g;
            *(float2*)(C + (size_t)r0 * 512 + col) = o0;
            *(float2*)(C + (size_t)(r0 + 8) * 512 + col) = o1;
        }
    }

    if (PROJ && (grow >> 14) < 2) {
        int t = grow >> 14;
        int h = bx * 2 + (wid & 1);
        #pragma unroll
        for (int mi = 0; mi < 2; mi++) {
            #pragma unroll
            for (int half = 0; half < 2; half++) {
                float s = 0.f;
                #pragma unroll
                for (int ni = 0; ni < 8; ni++) {
                    float x = acc[mi][ni][2 * half], y = acc[mi][ni][2 * half + 1];
                    s += x * x + y * y;
                }
                s += __shfl_xor_sync(0xffffffffu, s, 1);
                s += __shfl_xor_sync(0xffffffffu, s, 2);
                if (t4 == 0) {
                    int gr = grow + wm + mi * 16 + g + 8 * half;
                    int r = gr & 16383, bb = r >> 8, n = r & 255;
                    g_norms[t * 131072 + (h * 64 + bb) * 256 + n] = sqrtf(s);
                }
            }
        }
    }
}

// ---------------- 3) chunk statistics (fp32 SIMT) ----------------
__global__ __launch_bounds__(256) void stats_kernel()
{
    __shared__ float sE[256 * 64];
    __shared__ float red[256];
    __shared__ float smu[64];
    __shared__ float r3[3][8];

    int tid = threadIdx.x;
    int bx = blockIdx.x;
    int t = bx >> 9;
    int rest = bx & 511;
    int c = rest >> 3, s = rest & 7;
    int h = c >> 3, b = ((c & 7) << 3) + s;
    const float* base = g_f + (size_t)t * FS + (size_t)(b * 256) * 512 + h * 64;

    {
        int i = tid & 63, grp = tid >> 6;
        float sm = 0.f;
        for (int n = grp; n < 256; n += 4) sm += base[(size_t)n * 512 + i];
        red[tid] = sm;
        __syncthreads();
        if (tid < 64)
            smu[tid] = (red[tid] + red[tid + 64] + red[tid + 128] + red[tid + 192]) * (1.f / 256.f);
        __syncthreads();
    }

    for (int idx = tid; idx < 4096; idx += 256) {
        int n = idx >> 4, c4 = (idx & 15) * 4;
        float4 a = *(const float4*)(base + (size_t)n * 512 + c4);
        a.x -= smu[c4 + 0]; a.y -= smu[c4 + 1]; a.z -= smu[c4 + 2]; a.w -= smu[c4 + 3];
        *(float4*)&sE[n * 64 + c4] = a;
    }
    __syncthreads();

    int ti = tid >> 4, tj = tid & 15;
    float acc[4][4] = {};
    #pragma unroll 8
    for (int n = 0; n < 256; n++) {
        float4 a  = *(const float4*)&sE[n * 64 + ti * 4];
        float4 bb = *(const float4*)&sE[n * 64 + tj * 4];
        acc[0][0] += a.x * bb.x; acc[0][1] += a.x * bb.y; acc[0][2] += a.x * bb.z; acc[0][3] += a.x * bb.w;
        acc[1][0] += a.y * bb.x; acc[1][1] += a.y * bb.y; acc[1][2] += a.y * bb.z; acc[1][3] += a.y * bb.w;
        acc[2][0] += a.z * bb.x; acc[2][1] += a.z * bb.y; acc[2][2] += a.z * bb.z; acc[2][3] += a.z * bb.w;
        acc[3][0] += a.w * bb.x; acc[3][1] += a.w * bb.y; acc[3][2] += a.w * bb.z; acc[3][3] += a.w * bb.w;
    }

    float tot = 0.f, dsum = 0.f, vsum = 0.f;
    #pragma unroll
    for (int r = 0; r < 4; r++)
        #pragma unroll
        for (int r2 = 0; r2 < 4; r2++) tot += acc[r][r2] * acc[r][r2];
    if (ti == tj) {
        #pragma unroll
        for (int r = 0; r < 4; r++) {
            float gii = acc[r][r];
            dsum += gii * gii;
            float sig = sqrtf(gii * (1.f / 255.f) + 1e-8f);
            vsum += fmaxf(0.f, 1.f - sig);
        }
    }

    int w = tid >> 5, lane = tid & 31;
    float a0 = warp_sum(tot), a1 = warp_sum(dsum), a2 = warp_sum(vsum);
    if (!lane) { r3[0][w] = a0; r3[1][w] = a1; r3[2][w] = a2; }
    __syncthreads();
    if (tid == 0) {
        float T = 0.f, D = 0.f, V = 0.f;
        #pragma unroll
        for (int i = 0; i < 8; i++) { T += r3[0][i]; D += r3[1][i]; V += r3[2][i]; }
        g_part[bx * 2 + 0] = V * (1.f / 512.f);
        g_part[bx * 2 + 1] = (T - D) * (1.f / (255.f * 255.f * 64.f * 8.f));
    }
}

__global__ __launch_bounds__(256) void stats_reduce_kernel()
{
    int tid = threadIdx.x;
    int t = tid >> 7, c = (tid >> 1) & 63, comp = tid & 1;
    float v = 0.f;
    #pragma unroll
    for (int s = 0; s < 8; s++)
        v += g_part[((t * 512 + c * 8 + s) * 2) + comp];
    g_vc[t * 128 + comp * 64 + c] = v;
}

// ---------------- 4) QK^T tf32, 128x128 tile ----------------
__global__ __launch_bounds__(256) void qk_kernel(
    const float* __restrict__ cl, const float* __restrict__ vl)
{
    extern __shared__ float sh[];
    float* Qs = sh;              // [128][68]
    float* Ks = sh + 128 * 68;

    int tid = threadIdx.x, lane = tid & 31, wid = tid >> 5;
    int g = lane >> 2, t4 = lane & 3;
    int wm = (wid >> 1) * 32, wn = (wid & 1) * 64;
    int hb = blockIdx.z, h = hb >> 6, b = hb & 63, c = hb >> 3;
    int nt = blockIdx.y, mt = blockIdx.x;

    const float* qb = g_f + (size_t)(b * 256 + nt * 128) * 512 + h * 64;
    const float* kb = g_f + FS + (size_t)(b * 256 + mt * 128) * 512 + h * 64;
    int lrow = tid >> 4, lc4 = (tid & 15) * 4;

    #pragma unroll
    for (int l = 0; l < 8; l++) {
        int row = l * 16 + lrow;
        *(float4*)&Qs[row * 68 + lc4] = *(const float4*)(qb + (size_t)row * 512 + lc4);
        *(float4*)&Ks[row * 68 + lc4] = *(const float4*)(kb + (size_t)row * 512 + lc4);
    }
    __syncthreads();

    float acc[2][8][4] = {};
    #pragma unroll
    for (int ks = 0; ks < 8; ks++) {
        int kb8 = ks * 8;
        uint32_t af[2][4];
        #pragma unroll
        for (int mi = 0; mi < 2; mi++) {
            const float* ap = &Qs[(wm + mi * 16) * 68 + kb8];
            af[mi][0] = __float_as_uint(ap[g * 68 + t4]);
            af[mi][1] = __float_as_uint(ap[(g + 8) * 68 + t4]);
            af[mi][2] = __float_as_uint(ap[g * 68 + t4 + 4]);
            af[mi][3] = __float_as_uint(ap[(g + 8) * 68 + t4 + 4]);
        }
        #pragma unroll
        for (int ni = 0; ni < 8; ni++) {
            uint32_t b0 = __float_as_uint(Ks[(wn + ni * 8 + g) * 68 + kb8 + t4]);
            uint32_t b1 = __float_as_uint(Ks[(wn + ni * 8 + g) * 68 + kb8 + t4 + 4]);
            mma8(acc[0][ni], af[0], b0, b1);
            mma8(acc[1][ni], af[1], b0, b1);
        }
    }

    float cw = 1.f / (1.f + expf(-cl[0]));
    float vw = 1.f / (1.f + expf(-vl[0]));
    float cosw = 1.f - cw - vw;
    float biasv = cw * (g_vc[64 + c] * g_vc[192 + c]) + vw * (g_vc[c] * g_vc[128 + c]);

    float qs_[2][2];
    #pragma unroll
    for (int mi = 0; mi < 2; mi++)
        #pragma unroll
        for (int half = 0; half < 2; half++) {
            int n = nt * 128 + wm + mi * 16 + g + 8 * half;
            qs_[mi][half] = cosw / g_norms[hb * 256 + n];
        }

    float* sp = g_s + (size_t)hb * 65536;
    #pragma unroll
    for (int ni = 0; ni < 8; ni++) {
        int m0 = mt * 128 + wn + ni * 8 + 2 * t4;
        float ki0 = 1.f / g_norms[131072 + hb * 256 + m0];
        float ki1 = 1.f / g_norms[131072 + hb * 256 + m0 + 1];
        #pragma unroll
        for (int mi = 0; mi < 2; mi++) {
            #pragma unroll
            for (int half = 0; half < 2; half++) {
                int n = nt * 128 + wm + mi * 16 + g + 8 * half;
                float2 o = make_float2(
                    tf32r(qs_[mi][half] * acc[mi][ni][2 * half] * ki0 + biasv),
                    tf32r(qs_[mi][half] * acc[mi][ni][2 * half + 1] * ki1 + biasv));
                *(float2*)(sp + (size_t)n * 256 + m0) = o;
            }
        }
    }
}

// ---------------- 5) S@V tf32, 128x64 tile ----------------
__global__ __launch_bounds__(256) void sv_kernel()
{
    __shared__ float Ss[128 * 36];
    __shared__ float Vs[32 * 72];

    int tid = threadIdx.x, lane = tid & 31, wid = tid >> 5;
    int g = lane >> 2, t4 = lane & 3;
    int wm = (wid >> 1) * 32, wn = (wid & 1) * 32;
    int hb = blockIdx.y, h = hb >> 6, b = hb & 63;
    int rt = blockIdx.x;

    const float* sp = g_s + (size_t)hb * 65536 + (size_t)(rt * 128) * 256;
    const float* vb = g_f + 2 * FS + (size_t)(b * 256) * 512 + h * 64;

    int srow = tid >> 3, sc4 = (tid & 7) * 4;
    int vk = tid >> 4, vn4 = (tid & 15) * 4;

    float acc[2][4][4] = {};
    for (int mc = 0; mc < 8; mc++) {
        #pragma unroll
        for (int l = 0; l < 4; l++) {
            int row = l * 32 + srow;
            *(float4*)&Ss[row * 36 + sc4] =
                *(const float4*)(sp + (size_t)row * 256 + mc * 32 + sc4);
        }
        #pragma unroll
        for (int l = 0; l < 2; l++) {
            int k = l * 16 + vk;
            *(float4*)&Vs[k * 72 + vn4] =
                *(const float4*)(vb + (size_t)(mc * 32 + k) * 512 + vn4);
        }
        __syncthreads();
        #pragma unroll
        for (int ks = 0; ks < 4; ks++) {
            int kb8 = ks * 8;
            uint32_t af[2][4];
            #pragma unroll
            for (int mi = 0; mi < 2; mi++) {
                const float* ap = &Ss[(wm + mi * 16) * 36 + kb8];
                af[mi][0] = __float_as_uint(ap[g * 36 + t4]);
                af[mi][1] = __float_as_uint(ap[(g + 8) * 36 + t4]);
                af[mi][2] = __float_as_uint(ap[g * 36 + t4 + 4]);
                af[mi][3] = __float_as_uint(ap[(g + 8) * 36 + t4 + 4]);
            }
            #pragma unroll
            for (int ni = 0; ni < 4; ni++) {
                uint32_t b0 = __float_as_uint(Vs[(kb8 + t4) * 72 + wn + ni * 8 + g]);
                uint32_t b1 = __float_as_uint(Vs[(kb8 + t4 + 4) * 72 + wn + ni * 8 + g]);
                mma8(acc[0][ni], af[0], b0, b1);
                mma8(acc[1][ni], af[1], b0, b1);
            }
        }
        __syncthreads();
    }

    #pragma unroll
    for (int mi = 0; mi < 2; mi++) {
        #pragma unroll
        for (int ni = 0; ni < 4; ni++) {
            int col = wn + ni * 8 + 2 * t4;
            int n0 = rt * 128 + wm + mi * 16 + g;
            *(float2*)(g_att + (size_t)(b * 256 + n0) * 512 + h * 64 + col) =
                make_float2(tf32r(acc[mi][ni][0]), tf32r(acc[mi][ni][1]));
            *(float2*)(g_att + (size_t)(b * 256 + n0 + 8) * 512 + h * 64 + col) =
                make_float2(tf32r(acc[mi][ni][2]), tf32r(acc[mi][ni][3]));
        }
    }
}

// ---------------- launch ----------------
extern "C" void kernel_launch(void* const* d_in, const int* in_sizes, int n_in,
                              void* d_out, int out_size)
{
    const float* q   = (const float*)d_in[0];
    const float* k   = (const float*)d_in[1];
    const float* v   = (const float*)d_in[2];
    const float* gma = (const float*)d_in[3];
    const float* bta = (const float*)d_in[4];
    const float* Win = (const float*)d_in[5];
    const float* Wout= (const float*)d_in[6];
    const float* bout= (const float*)d_in[7];
    const float* covl= (const float*)d_in[8];
    const float* varl= (const float*)d_in[9];
    float* out = (float*)d_out;

    void *pxn, *pf, *patt, *pwin, *pwout;
    cudaGetSymbolAddress(&pxn, g_xn);
    cudaGetSymbolAddress(&pf, g_f);
    cudaGetSymbolAddress(&patt, g_att);
    cudaGetSymbolAddress(&pwin, g_win);
    cudaGetSymbolAddress(&pwout, g_wout);

    static bool attr_set = false;
    if (!attr_set) {
        cudaFuncSetAttribute(qk_kernel, cudaFuncAttributeMaxDynamicSharedMemorySize,
                             2 * 128 * 68 * 4);
        attr_set = true;
    }

    wround_kernel<<<256, 256>>>(Win, Wout);
    ln_kernel<<<6144, 256>>>(q, k, v, gma, bta);
    mm_kernel<true><<<dim3(4, 384), 256>>>((const float*)pxn, (const float*)pwin,
                                           (float*)pf, nullptr);
    stats_kernel<<<1024, 256>>>();
    stats_reduce_kernel<<<1, 256>>>();
    qk_kernel<<<dim3(2, 2, 512), 256, 2 * 128 * 68 * 4>>>(covl, varl);
    sv_kernel<<<dim3(2, 512), 256>>>();
    mm_kernel<false><<<dim3(4, 128), 256>>>((const float*)patt, (const float*)pwout,
                                            out, bout);
}

// round 5
// speedup vs baseline: 2.8443x; 1.0392x over previous
#include <cuda_runtime.h>
#include <math.h>
#include <stdint.h>

constexpr size_t FS = (size_t)16384 * 512;

__device__ float g_xn[3 * FS];                      // LN output (tf32-rounded)
__device__ float g_f[3 * FS];                       // projected features (tf32-rounded)
__device__ float g_att[FS];                         // attention out (tf32-rounded)
__device__ float g_win[512 * 512];
__device__ float g_wout[512 * 512];
__device__ float g_norms[2 * 512 * 256];            // qn,kn [t][hb][n]
__device__ float g_vc[256];                         // Vq,Cq,Vk,Ck
__device__ float g_part[2048];

__device__ __forceinline__ float warp_sum(float v) {
    #pragma unroll
    for (int o = 16; o; o >>= 1) v += __shfl_xor_sync(0xffffffffu, v, o);
    return v;
}
__device__ __forceinline__ float tf32r(float x) {
    uint32_t u;
    asm("cvt.rna.tf32.f32 %0, %1;" : "=r"(u) : "f"(x));
    return __uint_as_float(u);
}
__device__ __forceinline__ void mma8(float c[4], const uint32_t a[4], uint32_t b0, uint32_t b1) {
    asm volatile(
        "mma.sync.aligned.m16n8k8.row.col.f32.tf32.tf32.f32 "
        "{%0,%1,%2,%3},{%4,%5,%6,%7},{%8,%9},{%0,%1,%2,%3};"
        : "+f"(c[0]), "+f"(c[1]), "+f"(c[2]), "+f"(c[3])
        : "r"(a[0]), "r"(a[1]), "r"(a[2]), "r"(a[3]), "r"(b0), "r"(b1));
}

// ---------------- 0) round weights once ----------------
__global__ __launch_bounds__(256) void wround_kernel(
    const float* __restrict__ Win, const float* __restrict__ Wout)
{
    int idx = (blockIdx.x * 256 + threadIdx.x) * 4;
    float4 a = *(const float4*)(Win + idx);
    a.x = tf32r(a.x); a.y = tf32r(a.y); a.z = tf32r(a.z); a.w = tf32r(a.w);
    *(float4*)(g_win + idx) = a;
    float4 b = *(const float4*)(Wout + idx);
    b.x = tf32r(b.x); b.y = tf32r(b.y); b.z = tf32r(b.z); b.w = tf32r(b.w);
    *(float4*)(g_wout + idx) = b;
}

// ---------------- 1) LayerNorm, writes tf32-rounded output ----------------
__global__ __launch_bounds__(256) void ln_kernel(
    const float* __restrict__ q, const float* __restrict__ k, const float* __restrict__ v,
    const float* __restrict__ gma, const float* __restrict__ bta)
{
    int warp = threadIdx.x >> 5, lane = threadIdx.x & 31;
    int row = blockIdx.x * 8 + warp;
    int t = row >> 14, r = row & 16383;
    const float* src = (t == 0 ? q : (t == 1 ? k : v)) + (size_t)r * 512;
    float x[16], s = 0.f;
    #pragma unroll
    for (int i = 0; i < 16; i++) { x[i] = src[lane + 32 * i]; s += x[i]; }
    s = warp_sum(s);
    float mu = s * (1.f / 512.f), ss = 0.f;
    #pragma unroll
    for (int i = 0; i < 16; i++) { float d = x[i] - mu; ss += d * d; }
    ss = warp_sum(ss);
    float rs = rsqrtf(ss * (1.f / 512.f) + 1e-5f);
    float* dst = g_xn + (size_t)row * 512;
    #pragma unroll
    for (int i = 0; i < 16; i++) {
        int c = lane + 32 * i;
        dst[c] = tf32r((x[i] - mu) * rs * gma[c] + bta[c]);
    }
}

// ---------------- 2/6) tf32 GEMM 128x128, BK=16 ----------------
template<bool PROJ>
__global__ __launch_bounds__(256) void mm_kernel(
    const float* __restrict__ A, const float* __restrict__ B,
    float* __restrict__ C, const float* __restrict__ bias)
{
    __shared__ float As[2][128 * 20];
    __shared__ float Bs[2][16 * 136];

    int tid = threadIdx.x, lane = tid & 31, wid = tid >> 5;
    int g = lane >> 2, t4 = lane & 3;
    int wm = (wid >> 1) * 32, wn = (wid & 1) * 64;
    int bx = blockIdx.x;
    int grow = blockIdx.y * 128;

    int arow = tid >> 2, ac4 = (tid & 3) * 4;
    const float* srcA[2];
    #pragma unroll
    for (int l = 0; l < 2; l++)
        srcA[l] = A + (size_t)(grow + l * 64 + arow) * 512;
    const float* Bbase = B + (size_t)bx * 128 + lane * 4;

    float acc[2][8][4] = {};
    float4 pA[2], pB[2];

    #pragma unroll
    for (int l = 0; l < 2; l++) {
        *(float4*)&As[0][(l * 64 + arow) * 20 + ac4] = *(const float4*)(srcA[l] + ac4);
        *(float4*)&Bs[0][(l * 8 + wid) * 136 + lane * 4] =
            *(const float4*)(Bbase + (size_t)(l * 8 + wid) * 512);
    }
    __syncthreads();

    int buf = 0;
    for (int bk = 0; bk < 512; bk += 16) {
        bool more = (bk + 16) < 512;
        if (more) {
            #pragma unroll
            for (int l = 0; l < 2; l++) {
                pA[l] = *(const float4*)(srcA[l] + bk + 16 + ac4);
                pB[l] = *(const float4*)(Bbase + (size_t)(bk + 16 + l * 8 + wid) * 512);
            }
        }
        #pragma unroll
        for (int ks = 0; ks < 2; ks++) {
            int kb = ks * 8;
            uint32_t af[2][4];
            #pragma unroll
            for (int mi = 0; mi < 2; mi++) {
                const float* ap = &As[buf][(wm + mi * 16) * 20 + kb];
                af[mi][0] = __float_as_uint(ap[g * 20 + t4]);
                af[mi][1] = __float_as_uint(ap[(g + 8) * 20 + t4]);
                af[mi][2] = __float_as_uint(ap[g * 20 + t4 + 4]);
                af[mi][3] = __float_as_uint(ap[(g + 8) * 20 + t4 + 4]);
            }
            #pragma unroll
            for (int ni = 0; ni < 8; ni++) {
                uint32_t b0 = __float_as_uint(Bs[buf][(kb + t4) * 136 + wn + ni * 8 + g]);
                uint32_t b1 = __float_as_uint(Bs[buf][(kb + t4 + 4) * 136 + wn + ni * 8 + g]);
                mma8(acc[0][ni], af[0], b0, b1);
                mma8(acc[1][ni], af[1], b0, b1);
            }
        }
        if (more) {
            #pragma unroll
            for (int l = 0; l < 2; l++) {
                *(float4*)&As[buf ^ 1][(l * 64 + arow) * 20 + ac4] = pA[l];
                *(float4*)&Bs[buf ^ 1][(l * 8 + wid) * 136 + lane * 4] = pB[l];
            }
            __syncthreads();
            buf ^= 1;
        }
    }

    if (PROJ) {
        #pragma unroll
        for (int mi = 0; mi < 2; mi++)
            #pragma unroll
            for (int ni = 0; ni < 8; ni++)
                #pragma unroll
                for (int p = 0; p < 4; p++)
                    acc[mi][ni][p] = tf32r(acc[mi][ni][p]);
    }

    #pragma unroll
    for (int mi = 0; mi < 2; mi++) {
        #pragma unroll
        for (int ni = 0; ni < 8; ni++) {
            int col = bx * 128 + wn + ni * 8 + 2 * t4;
            float2 o0 = make_float2(acc[mi][ni][0], acc[mi][ni][1]);
            float2 o1 = make_float2(acc[mi][ni][2], acc[mi][ni][3]);
            if (!PROJ) {
                float2 bb = *(const float2*)(bias + col);
                o0.x += bb.x; o0.y += bb.y; o1.x += bb.x; o1.y += bb.y;
            }
            int r0 = grow + wm + mi * 16 + g;
            *(float2*)(C + (size_t)r0 * 512 + col) = o0;
            *(float2*)(C + (size_t)(r0 + 8) * 512 + col) = o1;
        }
    }

    if (PROJ && (grow >> 14) < 2) {
        int t = grow >> 14;
        int h = bx * 2 + (wid & 1);
        #pragma unroll
        for (int mi = 0; mi < 2; mi++) {
            #pragma unroll
            for (int half = 0; half < 2; half++) {
                float s = 0.f;
                #pragma unroll
                for (int ni = 0; ni < 8; ni++) {
                    float x = acc[mi][ni][2 * half], y = acc[mi][ni][2 * half + 1];
                    s += x * x + y * y;
                }
                s += __shfl_xor_sync(0xffffffffu, s, 1);
                s += __shfl_xor_sync(0xffffffffu, s, 2);
                if (t4 == 0) {
                    int gr = grow + wm + mi * 16 + g + 8 * half;
                    int r = gr & 16383, bb = r >> 8, n = r & 255;
                    g_norms[t * 131072 + (h * 64 + bb) * 256 + n] = sqrtf(s);
                }
            }
        }
    }
}

// ---------------- 3) chunk statistics: Gram via tf32 mma ----------------
__global__ __launch_bounds__(256) void stats_kernel()
{
    extern __shared__ float sh[];
    float* sE = sh;                 // [256][68]
    float* Gs = sh + 256 * 68;      // [64][66]
    __shared__ float red[256];
    __shared__ float smu[64];
    __shared__ float r3[3][8];

    int tid = threadIdx.x;
    int bx = blockIdx.x;
    int t = bx >> 9;
    int rest = bx & 511;
    int c = rest >> 3, s = rest & 7;
    int h = c >> 3, b = ((c & 7) << 3) + s;
    const float* base = g_f + (size_t)t * FS + (size_t)(b * 256) * 512 + h * 64;

    // load raw tile
    for (int idx = tid; idx < 4096; idx += 256) {
        int n = idx >> 4, c4 = (idx & 15) * 4;
        *(float4*)&sE[n * 68 + c4] = *(const float4*)(base + (size_t)n * 512 + c4);
    }
    __syncthreads();

    // column means from smem
    {
        int i = tid & 63, grp = tid >> 6;
        float sm = 0.f;
        #pragma unroll 8
        for (int n = grp; n < 256; n += 4) sm += sE[n * 68 + i];
        red[tid] = sm;
        __syncthreads();
        if (tid < 64)
            smu[tid] = (red[tid] + red[tid + 64] + red[tid + 128] + red[tid + 192]) * (1.f / 256.f);
        __syncthreads();
    }

    // center + tf32 round in place
    for (int idx = tid; idx < 4096; idx += 256) {
        int n = idx >> 4, c4 = (idx & 15) * 4;
        float4 a = *(float4*)&sE[n * 68 + c4];
        a.x = tf32r(a.x - smu[c4 + 0]);
        a.y = tf32r(a.y - smu[c4 + 1]);
        a.z = tf32r(a.z - smu[c4 + 2]);
        a.w = tf32r(a.w - smu[c4 + 3]);
        *(float4*)&sE[n * 68 + c4] = a;
    }
    __syncthreads();

    // Gram G = E^T E via mma: 8 warps, warp tile 16x32
    int lane = tid & 31, wid = tid >> 5;
    int g = lane >> 2, t4 = lane & 3;
    int wm = (wid & 3) * 16, wn = (wid >> 2) * 32;
    float gacc[4][4] = {};
    #pragma unroll 4
    for (int ks = 0; ks < 32; ks++) {
        int kb8 = ks * 8;
        uint32_t af[4];
        af[0] = __float_as_uint(sE[(kb8 + t4) * 68 + wm + g]);
        af[1] = __float_as_uint(sE[(kb8 + t4) * 68 + wm + g + 8]);
        af[2] = __float_as_uint(sE[(kb8 + t4 + 4) * 68 + wm + g]);
        af[3] = __float_as_uint(sE[(kb8 + t4 + 4) * 68 + wm + g + 8]);
        #pragma unroll
        for (int ni = 0; ni < 4; ni++) {
            uint32_t b0 = __float_as_uint(sE[(kb8 + t4) * 68 + wn + ni * 8 + g]);
            uint32_t b1 = __float_as_uint(sE[(kb8 + t4 + 4) * 68 + wn + ni * 8 + g]);
            mma8(gacc[ni], af, b0, b1);
        }
    }
    #pragma unroll
    for (int ni = 0; ni < 4; ni++) {
        int col = wn + ni * 8 + 2 * t4;
        *(float2*)&Gs[(wm + g) * 66 + col] = make_float2(gacc[ni][0], gacc[ni][1]);
        *(float2*)&Gs[(wm + g + 8) * 66 + col] = make_float2(gacc[ni][2], gacc[ni][3]);
    }
    __syncthreads();

    // reductions over G
    float tot = 0.f, dsum = 0.f, vsum = 0.f;
    #pragma unroll
    for (int l = 0; l < 16; l++) {
        int idx = tid * 16 + l;
        int r = idx >> 6, cc = idx & 63;
        float gv = Gs[r * 66 + cc];
        tot += gv * gv;
        if (r == cc) {
            dsum += gv * gv;
            float sig = sqrtf(gv * (1.f / 255.f) + 1e-8f);
            vsum += fmaxf(0.f, 1.f - sig);
        }
    }

    int w = tid >> 5, lane2 = tid & 31;
    float a0 = warp_sum(tot), a1 = warp_sum(dsum), a2 = warp_sum(vsum);
    if (!lane2) { r3[0][w] = a0; r3[1][w] = a1; r3[2][w] = a2; }
    __syncthreads();
    if (tid == 0) {
        float T = 0.f, D = 0.f, V = 0.f;
        #pragma unroll
        for (int i = 0; i < 8; i++) { T += r3[0][i]; D += r3[1][i]; V += r3[2][i]; }
        g_part[bx * 2 + 0] = V * (1.f / 512.f);
        g_part[bx * 2 + 1] = (T - D) * (1.f / (255.f * 255.f * 64.f * 8.f));
    }
}

__global__ __launch_bounds__(256) void stats_reduce_kernel()
{
    int tid = threadIdx.x;
    int t = tid >> 7, c = (tid >> 1) & 63, comp = tid & 1;
    float v = 0.f;
    #pragma unroll
    for (int s = 0; s < 8; s++)
        v += g_part[((t * 512 + c * 8 + s) * 2) + comp];
    g_vc[t * 128 + comp * 64 + c] = v;
}

// ---------------- 4) fused attention: QK^T -> epilogue -> S@V ----------------
__global__ __launch_bounds__(256) void attn_kernel(
    const float* __restrict__ cl, const float* __restrict__ vl)
{
    extern __shared__ float sh[];
    float* Qs  = sh;                       // [128][68]
    float* Ks  = sh + 128 * 68;            // [64][68]
    float* Vs  = sh + 128 * 68 + 64 * 68;  // [64][72]
    float* Ssm = Vs + 64 * 72;             // [128][68]

    int tid = threadIdx.x, lane = tid & 31, wid = tid >> 5;
    int g = lane >> 2, t4 = lane & 3;
    int wm = (wid >> 1) * 32, wn = (wid & 1) * 32;
    int nt = blockIdx.x, hb = blockIdx.y;
    int h = hb >> 6, b = hb & 63, c = hb >> 3;

    const float* qb = g_f + (size_t)(b * 256 + nt * 128) * 512 + h * 64;
    const float* kb = g_f + FS + (size_t)(b * 256) * 512 + h * 64;
    const float* vb = g_f + 2 * FS + (size_t)(b * 256) * 512 + h * 64;

    // load Q tile
    {
        int lrow = tid >> 4, lc4 = (tid & 15) * 4;
        #pragma unroll
        for (int l = 0; l < 8; l++) {
            int row = l * 16 + lrow;
            *(float4*)&Qs[row * 68 + lc4] = *(const float4*)(qb + (size_t)row * 512 + lc4);
        }
    }

    float cw = 1.f / (1.f + expf(-cl[0]));
    float vw = 1.f / (1.f + expf(-vl[0]));
    float cosw = 1.f - cw - vw;
    float biasv = cw * (g_vc[64 + c] * g_vc[192 + c]) + vw * (g_vc[c] * g_vc[128 + c]);

    float qinv[2][2];
    #pragma unroll
    for (int mi = 0; mi < 2; mi++)
        #pragma unroll
        for (int half = 0; half < 2; half++) {
            int n = nt * 128 + wm + mi * 16 + g + 8 * half;
            qinv[mi][half] = cosw / g_norms[hb * 256 + n];
        }

    int krow = tid >> 2;
    int kc0 = (tid & 3) * 4;

    float oacc[2][4][4] = {};
    for (int mc = 0; mc < 4; mc++) {
        // load K,V chunk [64][64]
        #pragma unroll
        for (int l = 0; l < 4; l++) {
            int col = kc0 + l * 16;
            *(float4*)&Ks[krow * 68 + col] =
                *(const float4*)(kb + (size_t)(mc * 64 + krow) * 512 + col);
            *(float4*)&Vs[krow * 72 + col] =
                *(const float4*)(vb + (size_t)(mc * 64 + krow) * 512 + col);
        }
        __syncthreads();

        // S = Q @ K^T  (128x64)
        float sacc[2][4][4] = {};
        #pragma unroll
        for (int ks = 0; ks < 8; ks++) {
            int kb8 = ks * 8;
            uint32_t af[2][4];
            #pragma unroll
            for (int mi = 0; mi < 2; mi++) {
                const float* ap = &Qs[(wm + mi * 16) * 68 + kb8];
                af[mi][0] = __float_as_uint(ap[g * 68 + t4]);
                af[mi][1] = __float_as_uint(ap[(g + 8) * 68 + t4]);
                af[mi][2] = __float_as_uint(ap[g * 68 + t4 + 4]);
                af[mi][3] = __float_as_uint(ap[(g + 8) * 68 + t4 + 4]);
            }
            #pragma unroll
            for (int ni = 0; ni < 4; ni++) {
                uint32_t b0 = __float_as_uint(Ks[(wn + ni * 8 + g) * 68 + kb8 + t4]);
                uint32_t b1 = __float_as_uint(Ks[(wn + ni * 8 + g) * 68 + kb8 + t4 + 4]);
                mma8(sacc[0][ni], af[0], b0, b1);
                mma8(sacc[1][ni], af[1], b0, b1);
            }
        }

        // epilogue -> Ssm (tf32 rounded)
        #pragma unroll
        for (int ni = 0; ni < 4; ni++) {
            int ml = wn + ni * 8 + 2 * t4;
            int m0 = mc * 64 + ml;
            float ki0 = 1.f / g_norms[131072 + hb * 256 + m0];
            float ki1 = 1.f / g_norms[131072 + hb * 256 + m0 + 1];
            #pragma unroll
            for (int mi = 0; mi < 2; mi++) {
                #pragma unroll
                for (int half = 0; half < 2; half++) {
                    int nl = wm + mi * 16 + g + 8 * half;
                    float2 o = make_float2(
                        tf32r(qinv[mi][half] * sacc[mi][ni][2 * half] * ki0 + biasv),
                        tf32r(qinv[mi][half] * sacc[mi][ni][2 * half + 1] * ki1 + biasv));
                    *(float2*)&Ssm[nl * 68 + ml] = o;
                }
            }
        }
        __syncthreads();

        // O += Ssm @ V
        #pragma unroll
        for (int ks = 0; ks < 8; ks++) {
            int kb8 = ks * 8;
            uint32_t af[2][4];
            #pragma unroll
            for (int mi = 0; mi < 2; mi++) {
                const float* ap = &Ssm[(wm + mi * 16) * 68 + kb8];
                af[mi][0] = __float_as_uint(ap[g * 68 + t4]);
                af[mi][1] = __float_as_uint(ap[(g + 8) * 68 + t4]);
                af[mi][2] = __float_as_uint(ap[g * 68 + t4 + 4]);
                af[mi][3] = __float_as_uint(ap[(g + 8) * 68 + t4 + 4]);
            }
            #pragma unroll
            for (int ni = 0; ni < 4; ni++) {
                uint32_t b0 = __float_as_uint(Vs[(kb8 + t4) * 72 + wn + ni * 8 + g]);
                uint32_t b1 = __float_as_uint(Vs[(kb8 + t4 + 4) * 72 + wn + ni * 8 + g]);
                mma8(oacc[0][ni], af[0], b0, b1);
                mma8(oacc[1][ni], af[1], b0, b1);
            }
        }
        __syncthreads();
    }

    #pragma unroll
    for (int mi = 0; mi < 2; mi++) {
        #pragma unroll
        for (int ni = 0; ni < 4; ni++) {
            int col = wn + ni * 8 + 2 * t4;
            int n0 = nt * 128 + wm + mi * 16 + g;
            *(float2*)(g_att + (size_t)(b * 256 + n0) * 512 + h * 64 + col) =
                make_float2(tf32r(oacc[mi][ni][0]), tf32r(oacc[mi][ni][1]));
            *(float2*)(g_att + (size_t)(b * 256 + n0 + 8) * 512 + h * 64 + col) =
                make_float2(tf32r(oacc[mi][ni][2]), tf32r(oacc[mi][ni][3]));
        }
    }
}

// ---------------- launch ----------------
extern "C" void kernel_launch(void* const* d_in, const int* in_sizes, int n_in,
                              void* d_out, int out_size)
{
    const float* q   = (const float*)d_in[0];
    const float* k   = (const float*)d_in[1];
    const float* v   = (const float*)d_in[2];
    const float* gma = (const float*)d_in[3];
    const float* bta = (const float*)d_in[4];
    const float* Win = (const float*)d_in[5];
    const float* Wout= (const float*)d_in[6];
    const float* bout= (const float*)d_in[7];
    const float* covl= (const float*)d_in[8];
    const float* varl= (const float*)d_in[9];
    float* out = (float*)d_out;

    void *pxn, *pf, *patt, *pwin, *pwout;
    cudaGetSymbolAddress(&pxn, g_xn);
    cudaGetSymbolAddress(&pf, g_f);
    cudaGetSymbolAddress(&patt, g_att);
    cudaGetSymbolAddress(&pwin, g_win);
    cudaGetSymbolAddress(&pwout, g_wout);

    constexpr int ATTN_SMEM  = (128 * 68 + 64 * 68 + 64 * 72 + 128 * 68) * 4;
    constexpr int STATS_SMEM = (256 * 68 + 64 * 66) * 4;

    static bool attr_set = false;
    if (!attr_set) {
        cudaFuncSetAttribute(attn_kernel, cudaFuncAttributeMaxDynamicSharedMemorySize, ATTN_SMEM);
        cudaFuncSetAttribute(stats_kernel, cudaFuncAttributeMaxDynamicSharedMemorySize, STATS_SMEM);
        attr_set = true;
    }

    wround_kernel<<<256, 256>>>(Win, Wout);
    ln_kernel<<<6144, 256>>>(q, k, v, gma, bta);
    mm_kernel<true><<<dim3(4, 384), 256>>>((const float*)pxn, (const float*)pwin,
                                           (float*)pf, nullptr);
    stats_kernel<<<1024, 256, STATS_SMEM>>>();
    stats_reduce_kernel<<<1, 256>>>();
    attn_kernel<<<dim3(2, 512), 256, ATTN_SMEM>>>(covl, varl);
    mm_kernel<false><<<dim3(4, 128), 256>>>((const float*)patt, (const float*)pwout,
                                            out, bout);
}